// round 2
// baseline (speedup 1.0000x reference)
#include <cuda_runtime.h>
#include <cstdint>
#include <cstddef>

#define DM 63
#define DD 64
#define NR_MAX 256
#define B_MAX 2048
#define TMAIN 128

typedef unsigned long long ull;

// ---- scratch (static __device__ globals; no runtime allocation) ----
__device__ float  g_Wt0[(size_t)NR_MAX * DM * DD];    // head-side W^T, padded (e=0 -> 0)
__device__ float2 g_Wd [(size_t)NR_MAX * DM * DD];    // tail-side W^T, duplicated pairs {w,w}
__device__ float g_off[2][NR_MAX * DD];               // mobius offset per relation
__device__ float g_off2[2][NR_MAX];                   // sum(off^2)
__device__ float g_th[B_MAX * DD];                    // transformed head per batch row
__device__ float g_thb[B_MAX];                        // tanh(bias_head[u])

__device__ __forceinline__ float gelu_exact(float x) {
    return 0.5f * x * (1.0f + erff(x * 0.70710678118654752f));
}

#define FMA2(d, a, b, c) asm("fma.rn.f32x2 %0, %1, %2, %3;" : "=l"(d) : "l"(a), "l"(b), "l"(c))
#define ADD2(d, a, b)    asm("add.rn.f32x2 %0, %1, %2;"     : "=l"(d) : "l"(a), "l"(b))
#define PACK2(d, lo, hi) asm("mov.b64 %0, {%1, %2};"        : "=l"(d) : "r"(__float_as_uint(lo)), "r"(__float_as_uint(hi)))
#define UNPK2(lo, hi, s) do { unsigned _ulo, _uhi; \
    asm("mov.b64 {%0, %1}, %2;" : "=r"(_ulo), "=r"(_uhi) : "l"(s)); \
    lo = __uint_as_float(_ulo); hi = __uint_as_float(_uhi); } while (0)

// block reduction over 64 threads (2 warps)
__device__ __forceinline__ float bred64(float v, volatile float* wsum, int lane, int wid) {
    #pragma unroll
    for (int o = 16; o; o >>= 1) v += __shfl_down_sync(0xffffffffu, v, o);
    if (lane == 0) wsum[wid] = v;
    __syncthreads();
    float r = wsum[0] + wsum[1];
    __syncthreads();
    return r;
}

// ============================================================================
// K1: per-relation precompute. grid (NR, 2), block 64.
//   Phase A: gelu(W) rows + 2/s^2 precomputed into shared (one sync).
//   Phase B: rank-1 Householder chain — per-thread, sync-free, ILP-4 dot.
// ============================================================================
__global__ void k_rel(const float* __restrict__ Wh,  const float* __restrict__ Wtt,
                      const float* __restrict__ rch, const float* __restrict__ dirh,
                      const float* __restrict__ rct, const float* __restrict__ dirt,
                      const float* __restrict__ fsh, const float* __restrict__ fst)
{
    int r    = blockIdx.x;
    int side = blockIdx.y;
    const float* Wemb = side ? Wtt  : Wh;
    const float* rc   = side ? rct  : rch;
    const float* dw   = side ? dirt : dirh;
    float fs          = side ? fst[0] : fsh[0];

    __shared__ float Wg[DM][DD];     // gelu(W): row j, comp k (padded stride)
    __shared__ float inv2s[DM];
    __shared__ float ws[DD];
    __shared__ float wsum[2];

    int tid = threadIdx.x;
    int lane = tid & 31, wid = tid >> 5;

    // Phase A: load + gelu all 63x63 weights
    const float* wbase = Wemb + (size_t)r * DM * DM;
    for (int idx = tid; idx < DM * DM; idx += 64) {
        int j = idx / DM, k = idx - j * DM;
        Wg[j][k] = gelu_exact(wbase[idx]);
    }
    __syncthreads();
    if (tid < DM) {
        float s0 = 0, s1 = 0, s2 = 0, s3 = 0;
        #pragma unroll
        for (int k = 0; k < 60; k += 4) {
            s0 = fmaf(Wg[tid][k    ], Wg[tid][k    ], s0);
            s1 = fmaf(Wg[tid][k + 1], Wg[tid][k + 1], s1);
            s2 = fmaf(Wg[tid][k + 2], Wg[tid][k + 2], s2);
            s3 = fmaf(Wg[tid][k + 3], Wg[tid][k + 3], s3);
        }
        s0 = fmaf(Wg[tid][60], Wg[tid][60], s0);
        s1 = fmaf(Wg[tid][61], Wg[tid][61], s1);
        s2 = fmaf(Wg[tid][62], Wg[tid][62], s2);
        float s = (s0 + s1) + (s2 + s3);
        inv2s[tid] = 2.0f / s;
    }
    __syncthreads();

    // Phase B: P row owned by thread tid (tid=63 computes harmless zeros)
    float prow[DM];
    #pragma unroll
    for (int k = 0; k < DM; k++) prow[k] = (k == tid) ? 1.0f : 0.0f;

    for (int j = 0; j < DM; j++) {
        const float* wj = Wg[j];
        float a0 = 0, a1 = 0, a2 = 0, a3 = 0;
        #pragma unroll
        for (int k = 0; k < 60; k += 4) {
            a0 = fmaf(prow[k    ], wj[k    ], a0);
            a1 = fmaf(prow[k + 1], wj[k + 1], a1);
            a2 = fmaf(prow[k + 2], wj[k + 2], a2);
            a3 = fmaf(prow[k + 3], wj[k + 3], a3);
        }
        a0 = fmaf(prow[60], wj[60], a0);
        a1 = fmaf(prow[61], wj[61], a1);
        a2 = fmaf(prow[62], wj[62], a2);
        float coef = ((a0 + a1) + (a2 + a3)) * inv2s[j];
        #pragma unroll
        for (int k = 0; k < DM; k++) prow[k] = fmaf(-coef, wj[k], prow[k]);
    }

    // store transposed + padded (col e=0 zero, flip on last column)
    if (side == 0) {
        float* base = &g_Wt0[(size_t)r * DM * DD];
        if (tid < DM) {
            #pragma unroll
            for (int c = 0; c < DM; c++) {
                float v = prow[c];
                if (c == DM - 1) v *= fs;
                base[(size_t)c * DD + 1 + tid] = v;
            }
        } else {
            for (int c = 0; c < DM; c++) base[(size_t)c * DD] = 0.0f;
        }
    } else {
        float2* base = &g_Wd[(size_t)r * DM * DD];
        if (tid < DM) {
            #pragma unroll
            for (int c = 0; c < DM; c++) {
                float v = prow[c];
                if (c == DM - 1) v *= fs;
                base[(size_t)c * DD + 1 + tid] = make_float2(v, v);
            }
        } else {
            for (int c = 0; c < DM; c++) base[(size_t)c * DD] = make_float2(0.0f, 0.0f);
        }
    }

    // ---- offset = expmap(c, 0.1 * normalize(d + <c,d> c)) ----
    float cv = rc[r * DD + tid];
    float dv = dw[r * DD + tid];
    float inner = bred64(cv * dv, wsum, lane, wid);
    float tv = fmaf(inner, cv, dv);
    float tn2 = bred64(tv * tv, wsum, lane, wid);
    tv = tv / (sqrtf(tn2) + 1e-6f);
    float uv = 0.1f * tv;
    float su2 = bred64(uv * uv, wsum, lane, wid);
    ws[tid] = uv;
    __syncthreads();
    float u0 = ws[0];
    float lin = su2 - 2.0f * u0 * u0;               // Minkowski inner
    float nrm = fminf(sqrtf(fmaxf(lin, 1e-8f)), 2.5f);
    float off = coshf(nrm) * cv + sinhf(nrm) * uv / nrm;
    g_off[side][r * DD + tid] = off;
    float off2 = bred64(off * off, wsum, lane, wid);
    if (tid == 0) g_off2[side][r] = off2;
}

// ============================================================================
// K2: head transform. grid B, block 64.
// ============================================================================
__global__ void k_th(const float* __restrict__ ent, const float* __restrict__ bias_head,
                     const int* __restrict__ u_idx, const int* __restrict__ r_idx)
{
    int b = blockIdx.x;
    int tid = threadIdx.x;
    int lane = tid & 31, wid = tid >> 5;
    __shared__ float xs[DD];
    __shared__ float wsum[2];
    int u = u_idx[b];
    int r = r_idx[b];
    xs[tid] = ent[(size_t)u * DD + tid];
    __syncthreads();
    float yv;
    if (tid == 0) {
        yv = xs[0];
    } else {
        const float* wrow = &g_Wt0[((size_t)r * DM + (tid - 1)) * DD];
        float a0 = 0, a1 = 0, a2 = 0, a3 = 0;
        #pragma unroll
        for (int e = 0; e < DD; e += 4) {
            a0 = fmaf(xs[e    ], wrow[e    ], a0);
            a1 = fmaf(xs[e + 1], wrow[e + 1], a1);
            a2 = fmaf(xs[e + 2], wrow[e + 2], a2);
            a3 = fmaf(xs[e + 3], wrow[e + 3], a3);
        }
        yv = (a0 + a1) + (a2 + a3);
    }
    float offv = g_off[0][r * DD + tid];
    float x2 = bred64(yv * yv, wsum, lane, wid);
    float xy = bred64(yv * offv, wsum, lane, wid);
    float y2 = g_off2[0][r];
    float A   = 1.0f + 2.0f * xy + y2;
    float Bc  = 1.0f - x2;
    float den = 1.0f + 2.0f * xy + x2 * y2 + 1e-15f;
    g_th[b * DD + tid] = fmaf(A, yv, Bc * offv) / den;
    if (tid == 0) g_thb[b] = tanhf(bias_head[u]);
}

// ============================================================================
// K3: main scoring. grid B, block 128. Two tails packed per f32x2 lane.
//   y = x @ Wr_t via FFMA2; epilogue fully algebraic (no y staging).
// ============================================================================
__global__ void __launch_bounds__(TMAIN) k_main(
    const float* __restrict__ ent, const float* __restrict__ bias_tail,
    const int* __restrict__ r_idx, const int* __restrict__ v_idx,
    float* __restrict__ out, int N)
{
    __shared__ __align__(16) float2 Wd_s[DM * DD];   // 32256 B, duplicated pairs
    __shared__ __align__(16) float2 offp[DD];        // {off,off}
    __shared__ __align__(16) float2 thp[DD];         // {th,th}
    __shared__ float off_f[DD], th_f[DD];

    int b = blockIdx.x;
    int tid = threadIdx.x;
    int r = r_idx[b];

    {
        const float4* src = (const float4*)&g_Wd[(size_t)r * DM * DD];
        float4* dst = (float4*)Wd_s;
        #pragma unroll 4
        for (int i = tid; i < DM * DD / 2; i += TMAIN) dst[i] = src[i];
    }
    if (tid < DD) {
        float ov = g_off[1][r * DD + tid];
        float tv = g_th[b * DD + tid];
        off_f[tid] = ov;  th_f[tid] = tv;
        offp[tid] = make_float2(ov, ov);
        thp[tid]  = make_float2(tv, tv);
    }
    float off2 = g_off2[1][r];
    float thb  = g_thb[b];
    __syncthreads();

    // per-block scalar constants over c>=1 (redundant per thread, broadcast LDS)
    float O2m = 0, OTm = 0, T2m = 0;
    #pragma unroll
    for (int c = 1; c < DD; c++) {
        float o = off_f[c], t = th_f[c];
        O2m = fmaf(o, o, O2m);
        OTm = fmaf(o, t, OTm);
        T2m = fmaf(t, t, T2m);
    }
    float off0 = off_f[0], th0 = th_f[0];

    const ull* Wull = (const ull*)Wd_s;
    const ull* offu = (const ull*)offp;
    const ull* thu  = (const ull*)thp;

    int npair = N >> 1;
    for (int p = tid; p < npair; p += TMAIN) {
        int vA = v_idx[b * N + 2 * p];
        int vB = v_idx[b * N + 2 * p + 1];
        const float4* xrA = (const float4*)(ent + (size_t)vA * DD);
        const float4* xrB = (const float4*)(ent + (size_t)vB * DD);

        ull xq[DD];
        float y0A, y0B;
        #pragma unroll
        for (int q = 0; q < 16; q++) {
            float4 a4 = xrA[q];
            float4 b4 = xrB[q];
            PACK2(xq[4 * q    ], a4.x, b4.x);
            PACK2(xq[4 * q + 1], a4.y, b4.y);
            PACK2(xq[4 * q + 2], a4.z, b4.z);
            PACK2(xq[4 * q + 3], a4.w, b4.w);
            if (q == 0) { y0A = a4.x; y0B = b4.x; }
        }

        ull syy, syo, syt = 0ULL;
        FMA2(syy, xq[0], xq[0], 0ULL);
        FMA2(syo, xq[0], offu[0], 0ULL);

        #pragma unroll 1
        for (int c = 0; c < DM; c++) {
            const ulonglong2* wr = (const ulonglong2*)(Wull + c * DD);
            ull a0 = 0ULL, a1 = 0ULL, a2 = 0ULL, a3 = 0ULL;
            #pragma unroll
            for (int q = 0; q < 32; q += 2) {
                ulonglong2 w0 = wr[q];
                ulonglong2 w1 = wr[q + 1];
                FMA2(a0, xq[2 * q    ], w0.x, a0);
                FMA2(a1, xq[2 * q + 1], w0.y, a1);
                FMA2(a2, xq[2 * q + 2], w1.x, a2);
                FMA2(a3, xq[2 * q + 3], w1.y, a3);
            }
            ull s01, s23, acc;
            ADD2(s01, a0, a1);
            ADD2(s23, a2, a3);
            ADD2(acc, s01, s23);
            FMA2(syy, acc, acc, syy);
            FMA2(syo, acc, offu[c + 1], syo);
            FMA2(syt, acc, thu[c + 1], syt);
        }

        float syyA, syyB, syoA, syoB, sytA, sytB;
        UNPK2(syyA, syyB, syy);
        UNPK2(syoA, syoB, syo);
        UNPK2(sytA, sytB, syt);

        float btA = tanhf(bias_tail[vA]);
        float btB = tanhf(bias_tail[vB]);

        // tail A
        {
            float A   = 1.0f + 2.0f * syoA + off2;
            float Bv  = 1.0f - syyA;
            float den = 1.0f + 2.0f * syoA + syyA * off2 + 1e-15f;
            float rd  = 1.0f / den;
            float a   = A * rd, bs = Bv * rd;
            float d0  = fmaf(a, y0A, fmaf(bs, off0, -th0));
            float cross = fmaf(bs, syoA - y0A * off0, -sytA);
            float bterm = fmaf(bs, fmaf(bs, O2m, -2.0f * OTm), T2m);
            float sum1  = fmaf(a * a, syyA - y0A * y0A, fmaf(2.0f * a, cross, bterm));
            float mkv   = sum1 - d0 * d0;
            out[(size_t)b * N + 2 * p] = 8.0f - mkv + thb + btA;
        }
        // tail B
        {
            float A   = 1.0f + 2.0f * syoB + off2;
            float Bv  = 1.0f - syyB;
            float den = 1.0f + 2.0f * syoB + syyB * off2 + 1e-15f;
            float rd  = 1.0f / den;
            float a   = A * rd, bs = Bv * rd;
            float d0  = fmaf(a, y0B, fmaf(bs, off0, -th0));
            float cross = fmaf(bs, syoB - y0B * off0, -sytB);
            float bterm = fmaf(bs, fmaf(bs, O2m, -2.0f * OTm), T2m);
            float sum1  = fmaf(a * a, syyB - y0B * y0B, fmaf(2.0f * a, cross, bterm));
            float mkv   = sum1 - d0 * d0;
            out[(size_t)b * N + 2 * p + 1] = 8.0f - mkv + thb + btB;
        }
    }
}

// ============================================================================
extern "C" void kernel_launch(void* const* d_in, const int* in_sizes, int n_in,
                              void* d_out, int out_size)
{
    (void)n_in; (void)out_size;
    const float* ent  = (const float*)d_in[0];
    const float* Wh   = (const float*)d_in[1];
    const float* Wtt  = (const float*)d_in[2];
    const float* rch  = (const float*)d_in[3];
    const float* dirh = (const float*)d_in[4];
    const float* rct  = (const float*)d_in[5];
    const float* dirt = (const float*)d_in[6];
    const float* bh   = (const float*)d_in[7];
    const float* bt   = (const float*)d_in[8];
    const float* fsh  = (const float*)d_in[9];
    const float* fst  = (const float*)d_in[10];
    const int* u_idx  = (const int*)d_in[11];
    const int* r_idx  = (const int*)d_in[12];
    const int* v_idx  = (const int*)d_in[13];
    float* out = (float*)d_out;

    int NR = in_sizes[3] / DD;       // 237
    int B  = in_sizes[11];           // 1024
    int N  = in_sizes[13] / B;       // 512

    k_rel<<<dim3(NR, 2), 64>>>(Wh, Wtt, rch, dirh, rct, dirt, fsh, fst);
    k_th<<<B, 64>>>(ent, bh, u_idx, r_idx);
    k_main<<<B, TMAIN>>>(ent, bt, r_idx, v_idx, out, N);
}

// round 3
// speedup vs baseline: 1.1965x; 1.1965x over previous
#include <cuda_runtime.h>
#include <cstdint>
#include <cstddef>

#define DM 63
#define DD 64
#define NR_MAX 256
#define B_MAX 2048
#define TMAIN 128

typedef unsigned long long ull;

// ---- scratch (static __device__ globals; no runtime allocation) ----
__device__ float g_Wt[2][(size_t)NR_MAX * DM * DD];   // W^T, padded: [side][r][c][e], e=0 -> 0
__device__ float g_off[2][NR_MAX * DD];               // mobius offset per relation
__device__ float g_off2[2][NR_MAX];                   // sum(off^2)
__device__ float g_th[B_MAX * DD];                    // transformed head per batch row
__device__ float g_thb[B_MAX];                        // tanh(bias_head[u])

__device__ __forceinline__ float gelu_exact(float x) {
    return 0.5f * x * (1.0f + erff(x * 0.70710678118654752f));
}

#define FMA2(d, a, b, c) asm("fma.rn.f32x2 %0, %1, %2, %3;" : "=l"(d) : "l"(a), "l"(b), "l"(c))
#define ADD2(d, a, b)    asm("add.rn.f32x2 %0, %1, %2;"     : "=l"(d) : "l"(a), "l"(b))
#define UNPK2(lo, hi, s) do { unsigned _ulo, _uhi; \
    asm("mov.b64 {%0, %1}, %2;" : "=r"(_ulo), "=r"(_uhi) : "l"(s)); \
    lo = __uint_as_float(_ulo); hi = __uint_as_float(_uhi); } while (0)

// block reduction over 64 threads (2 warps)
__device__ __forceinline__ float bred64(float v, volatile float* wsum, int lane, int wid) {
    #pragma unroll
    for (int o = 16; o; o >>= 1) v += __shfl_down_sync(0xffffffffu, v, o);
    if (lane == 0) wsum[wid] = v;
    __syncthreads();
    float r = wsum[0] + wsum[1];
    __syncthreads();
    return r;
}

// ============================================================================
// K1: per-relation precompute. grid (NR, 2), block 64.
//   Phase A: gelu(W) rows + 2/s^2 precomputed into shared (one sync).
//   Phase B: rank-1 Householder chain — per-thread, sync-free, ILP-4 dot.
// ============================================================================
__global__ void k_rel(const float* __restrict__ Wh,  const float* __restrict__ Wtt,
                      const float* __restrict__ rch, const float* __restrict__ dirh,
                      const float* __restrict__ rct, const float* __restrict__ dirt,
                      const float* __restrict__ fsh, const float* __restrict__ fst)
{
    int r    = blockIdx.x;
    int side = blockIdx.y;
    const float* Wemb = side ? Wtt  : Wh;
    const float* rc   = side ? rct  : rch;
    const float* dw   = side ? dirt : dirh;
    float fs          = side ? fst[0] : fsh[0];

    __shared__ float Wg[DM][DD];     // gelu(W): row j, comp k (padded stride)
    __shared__ float inv2s[DM];
    __shared__ float ws[DD];
    __shared__ float wsum[2];

    int tid = threadIdx.x;
    int lane = tid & 31, wid = tid >> 5;

    // Phase A: load + gelu all 63x63 weights
    const float* wbase = Wemb + (size_t)r * DM * DM;
    for (int idx = tid; idx < DM * DM; idx += 64) {
        int j = idx / DM, k = idx - j * DM;
        Wg[j][k] = gelu_exact(wbase[idx]);
    }
    __syncthreads();
    if (tid < DM) {
        float s0 = 0, s1 = 0, s2 = 0, s3 = 0;
        #pragma unroll
        for (int k = 0; k < 60; k += 4) {
            s0 = fmaf(Wg[tid][k    ], Wg[tid][k    ], s0);
            s1 = fmaf(Wg[tid][k + 1], Wg[tid][k + 1], s1);
            s2 = fmaf(Wg[tid][k + 2], Wg[tid][k + 2], s2);
            s3 = fmaf(Wg[tid][k + 3], Wg[tid][k + 3], s3);
        }
        s0 = fmaf(Wg[tid][60], Wg[tid][60], s0);
        s1 = fmaf(Wg[tid][61], Wg[tid][61], s1);
        s2 = fmaf(Wg[tid][62], Wg[tid][62], s2);
        float s = (s0 + s1) + (s2 + s3);
        inv2s[tid] = 2.0f / s;
    }
    __syncthreads();

    // Phase B: P row owned by thread tid (tid=63 computes harmless zeros)
    float prow[DM];
    #pragma unroll
    for (int k = 0; k < DM; k++) prow[k] = (k == tid) ? 1.0f : 0.0f;

    for (int j = 0; j < DM; j++) {
        const float* wj = Wg[j];
        float a0 = 0, a1 = 0, a2 = 0, a3 = 0;
        #pragma unroll
        for (int k = 0; k < 60; k += 4) {
            a0 = fmaf(prow[k    ], wj[k    ], a0);
            a1 = fmaf(prow[k + 1], wj[k + 1], a1);
            a2 = fmaf(prow[k + 2], wj[k + 2], a2);
            a3 = fmaf(prow[k + 3], wj[k + 3], a3);
        }
        a0 = fmaf(prow[60], wj[60], a0);
        a1 = fmaf(prow[61], wj[61], a1);
        a2 = fmaf(prow[62], wj[62], a2);
        float coef = ((a0 + a1) + (a2 + a3)) * inv2s[j];
        #pragma unroll
        for (int k = 0; k < DM; k++) prow[k] = fmaf(-coef, wj[k], prow[k]);
    }

    // store transposed + padded (col e=0 zero, flip on last column)
    float* base = &g_Wt[side][(size_t)r * DM * DD];
    if (tid < DM) {
        #pragma unroll
        for (int c = 0; c < DM; c++) {
            float v = prow[c];
            if (c == DM - 1) v *= fs;
            base[(size_t)c * DD + 1 + tid] = v;
        }
    } else {
        for (int c = 0; c < DM; c++) base[(size_t)c * DD] = 0.0f;
    }

    // ---- offset = expmap(c, 0.1 * normalize(d + <c,d> c)) ----
    float cv = rc[r * DD + tid];
    float dv = dw[r * DD + tid];
    float inner = bred64(cv * dv, wsum, lane, wid);
    float tv = fmaf(inner, cv, dv);
    float tn2 = bred64(tv * tv, wsum, lane, wid);
    tv = tv / (sqrtf(tn2) + 1e-6f);
    float uv = 0.1f * tv;
    float su2 = bred64(uv * uv, wsum, lane, wid);
    ws[tid] = uv;
    __syncthreads();
    float u0 = ws[0];
    float lin = su2 - 2.0f * u0 * u0;               // Minkowski inner
    float nrm = fminf(sqrtf(fmaxf(lin, 1e-8f)), 2.5f);
    float off = coshf(nrm) * cv + sinhf(nrm) * uv / nrm;
    g_off[side][r * DD + tid] = off;
    float off2 = bred64(off * off, wsum, lane, wid);
    if (tid == 0) g_off2[side][r] = off2;
}

// ============================================================================
// K2: head transform. grid B, block 64.
// ============================================================================
__global__ void k_th(const float* __restrict__ ent, const float* __restrict__ bias_head,
                     const int* __restrict__ u_idx, const int* __restrict__ r_idx)
{
    int b = blockIdx.x;
    int tid = threadIdx.x;
    int lane = tid & 31, wid = tid >> 5;
    __shared__ float xs[DD];
    __shared__ float wsum[2];
    int u = u_idx[b];
    int r = r_idx[b];
    xs[tid] = ent[(size_t)u * DD + tid];
    __syncthreads();
    float yv;
    if (tid == 0) {
        yv = xs[0];
    } else {
        const float* wrow = &g_Wt[0][((size_t)r * DM + (tid - 1)) * DD];
        float a0 = 0, a1 = 0, a2 = 0, a3 = 0;
        #pragma unroll
        for (int e = 0; e < DD; e += 4) {
            a0 = fmaf(xs[e    ], wrow[e    ], a0);
            a1 = fmaf(xs[e + 1], wrow[e + 1], a1);
            a2 = fmaf(xs[e + 2], wrow[e + 2], a2);
            a3 = fmaf(xs[e + 3], wrow[e + 3], a3);
        }
        yv = (a0 + a1) + (a2 + a3);
    }
    float offv = g_off[0][r * DD + tid];
    float x2 = bred64(yv * yv, wsum, lane, wid);
    float xy = bred64(yv * offv, wsum, lane, wid);
    float y2 = g_off2[0][r];
    float A   = 1.0f + 2.0f * xy + y2;
    float Bc  = 1.0f - x2;
    float den = 1.0f + 2.0f * xy + x2 * y2 + 1e-15f;
    g_th[b * DD + tid] = fmaf(A, yv, Bc * offv) / den;
    if (tid == 0) g_thb[b] = tanhf(bias_head[u]);
}

// ============================================================================
// K3: main scoring. grid B, block 128, one tail per thread per pass.
//   f32x2 packing along the FEATURE axis: {x_e, x_{e+1}} — pure reinterpret of
//   the float4 loads, xq = 32 ull = 64 regs (no spills). One horizontal FADD
//   per output c. Algebraic epilogue (no y staging, no second pass).
// ============================================================================
__global__ void __launch_bounds__(TMAIN) k_main(
    const float* __restrict__ ent, const float* __restrict__ bias_tail,
    const int* __restrict__ r_idx, const int* __restrict__ v_idx,
    float* __restrict__ out, int N)
{
    __shared__ __align__(16) float Wt_s[DM * DD];   // 16128 B
    __shared__ float off_f[DD], th_f[DD];

    int b = blockIdx.x;
    int tid = threadIdx.x;
    int r = r_idx[b];

    {
        const float4* src = (const float4*)&g_Wt[1][(size_t)r * DM * DD];
        float4* dst = (float4*)Wt_s;
        #pragma unroll 4
        for (int i = tid; i < DM * DD / 4; i += TMAIN) dst[i] = src[i];
    }
    if (tid < DD) {
        off_f[tid] = g_off[1][r * DD + tid];
        th_f[tid]  = g_th[b * DD + tid];
    }
    float off2 = g_off2[1][r];
    float thb  = g_thb[b];
    __syncthreads();

    // per-block scalar constants over c>=1 (redundant per thread, broadcast LDS)
    float O2m = 0, OTm = 0, T2m = 0;
    #pragma unroll
    for (int c = 1; c < DD; c++) {
        float o = off_f[c], t = th_f[c];
        O2m = fmaf(o, o, O2m);
        OTm = fmaf(o, t, OTm);
        T2m = fmaf(t, t, T2m);
    }
    float off0 = off_f[0], th0 = th_f[0];

    for (int n = tid; n < N; n += TMAIN) {
        int v = v_idx[b * N + n];
        const float4* xr = (const float4*)(ent + (size_t)v * DD);

        // x as 32 ull holding {x_e, x_{e+1}} pairs — straight reinterpret
        union { float4 f4[16]; ull u[32]; float f[64]; } xq;
        #pragma unroll
        for (int q = 0; q < 16; q++) xq.f4[q] = xr[q];
        float y0 = xq.f[0];

        float syy = y0 * y0;   // includes c=0 term
        float syo = y0 * off0; // includes c=0 term
        float syt = 0.0f;      // c>=1 only

        #pragma unroll 3
        for (int c = 0; c < DM; c++) {
            const ulonglong2* wr = (const ulonglong2*)(Wt_s + c * DD);
            ull a0 = 0ULL, a1 = 0ULL, a2 = 0ULL, a3 = 0ULL;
            #pragma unroll
            for (int q = 0; q < 16; q += 2) {
                ulonglong2 w0 = wr[q];        // broadcast LDS.128
                ulonglong2 w1 = wr[q + 1];
                FMA2(a0, xq.u[2 * q    ], w0.x, a0);
                FMA2(a1, xq.u[2 * q + 1], w0.y, a1);
                FMA2(a2, xq.u[2 * q + 2], w1.x, a2);
                FMA2(a3, xq.u[2 * q + 3], w1.y, a3);
            }
            ull s01, s23, sall;
            ADD2(s01, a0, a1);
            ADD2(s23, a2, a3);
            ADD2(sall, s01, s23);
            float lo, hi;
            UNPK2(lo, hi, sall);              // register view: no mov needed
            float yc = lo + hi;
            syy = fmaf(yc, yc, syy);
            syo = fmaf(yc, off_f[c + 1], syo);
            syt = fmaf(yc, th_f[c + 1], syt);
        }

        float A   = 1.0f + 2.0f * syo + off2;
        float Bv  = 1.0f - syy;
        float den = 1.0f + 2.0f * syo + syy * off2 + 1e-15f;
        float rd  = 1.0f / den;
        float a   = A * rd, bs = Bv * rd;
        float d0  = fmaf(a, y0, fmaf(bs, off0, -th0));
        float cross = fmaf(bs, syo - y0 * off0, -syt);
        float bterm = fmaf(bs, fmaf(bs, O2m, -2.0f * OTm), T2m);
        float sum1  = fmaf(a * a, syy - y0 * y0, fmaf(2.0f * a, cross, bterm));
        float mkv   = sum1 - d0 * d0;

        float btv = tanhf(bias_tail[v]);
        out[(size_t)b * N + n] = 8.0f - mkv + thb + btv;
    }
}

// ============================================================================
extern "C" void kernel_launch(void* const* d_in, const int* in_sizes, int n_in,
                              void* d_out, int out_size)
{
    (void)n_in; (void)out_size;
    const float* ent  = (const float*)d_in[0];
    const float* Wh   = (const float*)d_in[1];
    const float* Wtt  = (const float*)d_in[2];
    const float* rch  = (const float*)d_in[3];
    const float* dirh = (const float*)d_in[4];
    const float* rct  = (const float*)d_in[5];
    const float* dirt = (const float*)d_in[6];
    const float* bh   = (const float*)d_in[7];
    const float* bt   = (const float*)d_in[8];
    const float* fsh  = (const float*)d_in[9];
    const float* fst  = (const float*)d_in[10];
    const int* u_idx  = (const int*)d_in[11];
    const int* r_idx  = (const int*)d_in[12];
    const int* v_idx  = (const int*)d_in[13];
    float* out = (float*)d_out;

    int NR = in_sizes[3] / DD;       // 237
    int B  = in_sizes[11];           // 1024
    int N  = in_sizes[13] / B;       // 512

    k_rel<<<dim3(NR, 2), 64>>>(Wh, Wtt, rch, dirh, rct, dirt, fsh, fst);
    k_th<<<B, 64>>>(ent, bh, u_idx, r_idx);
    k_main<<<B, TMAIN>>>(ent, bt, r_idx, v_idx, out, N);
}

// round 4
// speedup vs baseline: 2.7726x; 2.3173x over previous
#include <cuda_runtime.h>
#include <cstdint>
#include <cstddef>

#define DM 63
#define DD 64
#define NR_MAX 256
#define B_MAX 2048
#define TMAIN 128

// ---- scratch (static __device__ globals; no runtime allocation) ----
__device__ float g_Wg[2][(size_t)NR_MAX * DM * DD];   // gelu(W): [side][r][j][k], k=63 pad -> 0
__device__ float g_Wt[2][(size_t)NR_MAX * DM * DD];   // W^T, padded: [side][r][c][e], e=0 -> 0
__device__ float g_off[2][NR_MAX * DD];               // mobius offset per relation
__device__ float g_off2[2][NR_MAX];                   // sum(off^2)
__device__ float g_p63[NR_MAX * DD];                  // tail: unscaled last col of P, [0]=0
__device__ float g_ofu[NR_MAX * DD];                  // tail: W @ off_sp, [0]=off0
__device__ float g_th[B_MAX * DD];                    // transformed head per batch row
__device__ float g_ttl[B_MAX * DD];                   // tail: W_t @ th_sp per b, [0]=0
__device__ float g_thb[B_MAX];                        // tanh(bias_head[u])

__device__ __forceinline__ float gelu_exact(float x) {
    return 0.5f * x * (1.0f + erff(x * 0.70710678118654752f));
}

// block reduction over 64 threads (2 warps)
__device__ __forceinline__ float bred64(float v, volatile float* wsum, int lane, int wid) {
    #pragma unroll
    for (int o = 16; o; o >>= 1) v += __shfl_down_sync(0xffffffffu, v, o);
    if (lane == 0) wsum[wid] = v;
    __syncthreads();
    float r = wsum[0] + wsum[1];
    __syncthreads();
    return r;
}

// ============================================================================
// K0: fully-parallel gelu of all relation weights (pulls erff out of k_rel)
// ============================================================================
__global__ void k_gelu(const float* __restrict__ Wh, const float* __restrict__ Wtt, int NR)
{
    int i = blockIdx.x * blockDim.x + threadIdx.x;
    int total = 2 * NR * DM * DD;
    if (i >= total) return;
    int k  = i & (DD - 1);
    int j  = (i >> 6) % DM;
    int rs = i / (DM * DD);
    int r  = rs % NR;
    int side = rs / NR;
    float v = 0.0f;
    if (k < DM) {
        const float* src = side ? Wtt : Wh;
        v = gelu_exact(src[(size_t)r * DM * DM + j * DM + k]);
    }
    g_Wg[side][(size_t)r * DM * DD + j * DD + k] = v;
}

// ============================================================================
// K1: per-relation precompute. grid (NR, 2), block 64.
//   Householder chain via rank-1 updates; also emits p63 and o~ = W @ off_sp
//   for the tail side (orthogonality-based scoring).
// ============================================================================
__global__ void k_rel(const float* __restrict__ rch, const float* __restrict__ dirh,
                      const float* __restrict__ rct, const float* __restrict__ dirt,
                      const float* __restrict__ fsh, const float* __restrict__ fst)
{
    int r    = blockIdx.x;
    int side = blockIdx.y;
    const float* rc = side ? rct  : rch;
    const float* dw = side ? dirt : dirh;
    float fs        = side ? fst[0] : fsh[0];

    __shared__ __align__(16) float Wg[DM * DD];
    __shared__ float inv2s[DM];
    __shared__ float ws[DD];
    __shared__ float wsum[2];

    int tid = threadIdx.x;
    int lane = tid & 31, wid = tid >> 5;

    // stage gelu'd weights from global (computed by k_gelu)
    {
        const float4* src = (const float4*)&g_Wg[side][(size_t)r * DM * DD];
        float4* dst = (float4*)Wg;
        for (int i = tid; i < DM * DD / 4; i += 64) dst[i] = src[i];
    }
    __syncthreads();
    if (tid < DM) {
        const float* row = Wg + tid * DD;
        float s0 = 0, s1 = 0, s2 = 0, s3 = 0;
        #pragma unroll
        for (int k = 0; k < 60; k += 4) {
            s0 = fmaf(row[k    ], row[k    ], s0);
            s1 = fmaf(row[k + 1], row[k + 1], s1);
            s2 = fmaf(row[k + 2], row[k + 2], s2);
            s3 = fmaf(row[k + 3], row[k + 3], s3);
        }
        s0 = fmaf(row[60], row[60], s0);
        s1 = fmaf(row[61], row[61], s1);
        s2 = fmaf(row[62], row[62], s2);
        inv2s[tid] = 2.0f / ((s0 + s1) + (s2 + s3));
    }
    __syncthreads();

    // Householder chain: thread tid owns P row tid (tid=63 computes zeros)
    float prow[DM];
    #pragma unroll
    for (int k = 0; k < DM; k++) prow[k] = (k == tid) ? 1.0f : 0.0f;

    for (int j = 0; j < DM; j++) {
        const float* wj = Wg + j * DD;
        float a0 = 0, a1 = 0, a2 = 0, a3 = 0;
        #pragma unroll
        for (int k = 0; k < 60; k += 4) {
            a0 = fmaf(prow[k    ], wj[k    ], a0);
            a1 = fmaf(prow[k + 1], wj[k + 1], a1);
            a2 = fmaf(prow[k + 2], wj[k + 2], a2);
            a3 = fmaf(prow[k + 3], wj[k + 3], a3);
        }
        a0 = fmaf(prow[60], wj[60], a0);
        a1 = fmaf(prow[61], wj[61], a1);
        a2 = fmaf(prow[62], wj[62], a2);
        float coef = ((a0 + a1) + (a2 + a3)) * inv2s[j];
        #pragma unroll
        for (int k = 0; k < DM; k++) prow[k] = fmaf(-coef, wj[k], prow[k]);
    }

    float p63v = prow[62];       // unscaled last column entry
    prow[62] *= fs;              // apply flip scale for all W uses below

    // store W^T padded ([c][e] layout, e=0 col zero)
    {
        float* base = &g_Wt[side][(size_t)r * DM * DD];
        if (tid < DM) {
            #pragma unroll
            for (int c = 0; c < DM; c++) base[(size_t)c * DD + 1 + tid] = prow[c];
        } else {
            for (int c = 0; c < DM; c++) base[(size_t)c * DD] = 0.0f;
        }
    }

    // ---- offset = expmap(c, 0.1 * normalize(d + <c,d> c)) ----
    float cv = rc[r * DD + tid];
    float dv = dw[r * DD + tid];
    float inner = bred64(cv * dv, wsum, lane, wid);
    float tv = fmaf(inner, cv, dv);
    float tn2 = bred64(tv * tv, wsum, lane, wid);
    tv = tv / (sqrtf(tn2) + 1e-6f);
    float uv = 0.1f * tv;
    float su2 = bred64(uv * uv, wsum, lane, wid);
    ws[tid] = uv;
    __syncthreads();
    float u0 = ws[0];
    float lin = su2 - 2.0f * u0 * u0;               // Minkowski inner
    float nrm = fminf(sqrtf(fmaxf(lin, 1e-8f)), 2.5f);
    float off = coshf(nrm) * cv + sinhf(nrm) * uv / nrm;
    g_off[side][r * DD + tid] = off;
    float off2 = bred64(off * off, wsum, lane, wid);
    if (tid == 0) g_off2[side][r] = off2;

    if (side == 1) {
        __syncthreads();
        ws[tid] = off;           // full offset vector in shared
        __syncthreads();
        if (tid < DM) {
            // o~_tid = sum_c W[tid][c] * off_sp[c]
            float a0 = 0, a1 = 0, a2 = 0, a3 = 0;
            #pragma unroll
            for (int c = 0; c < 60; c += 4) {
                a0 = fmaf(prow[c    ], ws[c + 1], a0);
                a1 = fmaf(prow[c + 1], ws[c + 2], a1);
                a2 = fmaf(prow[c + 2], ws[c + 3], a2);
                a3 = fmaf(prow[c + 3], ws[c + 4], a3);
            }
            a0 = fmaf(prow[60], ws[61], a0);
            a1 = fmaf(prow[61], ws[62], a1);
            a2 = fmaf(prow[62], ws[63], a2);
            g_ofu[r * DD + 1 + tid] = (a0 + a1) + (a2 + a3);
            g_p63[r * DD + 1 + tid] = p63v;
        } else {
            g_ofu[r * DD] = ws[0];   // off0 folded in
            g_p63[r * DD] = 0.0f;
        }
    }
}

// ============================================================================
// K2: head transform + per-b tail projection t~ = W_t @ th_sp. grid B, block 64.
// ============================================================================
__global__ void k_th(const float* __restrict__ ent, const float* __restrict__ bias_head,
                     const int* __restrict__ u_idx, const int* __restrict__ r_idx)
{
    int b = blockIdx.x;
    int tid = threadIdx.x;
    int lane = tid & 31, wid = tid >> 5;
    __shared__ float xs[DD];
    __shared__ float wsum[2];
    int u = u_idx[b];
    int r = r_idx[b];
    xs[tid] = ent[(size_t)u * DD + tid];
    __syncthreads();
    float yv;
    if (tid == 0) {
        yv = xs[0];
    } else {
        const float* wrow = &g_Wt[0][((size_t)r * DM + (tid - 1)) * DD];
        float a0 = 0, a1 = 0, a2 = 0, a3 = 0;
        #pragma unroll
        for (int e = 0; e < DD; e += 4) {
            a0 = fmaf(xs[e    ], wrow[e    ], a0);
            a1 = fmaf(xs[e + 1], wrow[e + 1], a1);
            a2 = fmaf(xs[e + 2], wrow[e + 2], a2);
            a3 = fmaf(xs[e + 3], wrow[e + 3], a3);
        }
        yv = (a0 + a1) + (a2 + a3);
    }
    float offv = g_off[0][r * DD + tid];
    float x2 = bred64(yv * yv, wsum, lane, wid);
    float xy = bred64(yv * offv, wsum, lane, wid);
    float y2 = g_off2[0][r];
    float A   = 1.0f + 2.0f * xy + y2;
    float Bc  = 1.0f - x2;
    float den = 1.0f + 2.0f * xy + x2 * y2 + 1e-15f;
    float th  = fmaf(A, yv, Bc * offv) / den;
    g_th[b * DD + tid] = th;
    if (tid == 0) g_thb[b] = tanhf(bias_head[u]);

    // t~_d = sum_c W_t[d][c] * th_sp[c]   (coalesced: g_Wt[1][r][c][1+d])
    __syncthreads();
    xs[tid] = th;
    __syncthreads();
    const float* base1 = &g_Wt[1][(size_t)r * DM * DD];
    if (tid < DM) {
        float a0 = 0, a1 = 0, a2 = 0, a3 = 0;
        #pragma unroll 4
        for (int c = 0; c < 60; c += 4) {
            a0 = fmaf(base1[(c    ) * DD + 1 + tid], xs[c + 1], a0);
            a1 = fmaf(base1[(c + 1) * DD + 1 + tid], xs[c + 2], a1);
            a2 = fmaf(base1[(c + 2) * DD + 1 + tid], xs[c + 3], a2);
            a3 = fmaf(base1[(c + 3) * DD + 1 + tid], xs[c + 4], a3);
        }
        a0 = fmaf(base1[60 * DD + 1 + tid], xs[61], a0);
        a1 = fmaf(base1[61 * DD + 1 + tid], xs[62], a1);
        a2 = fmaf(base1[62 * DD + 1 + tid], xs[63], a2);
        g_ttl[b * DD + 1 + tid] = (a0 + a1) + (a2 + a3);
    } else {
        g_ttl[b * DD] = 0.0f;
    }
}

// ============================================================================
// K3: main scoring. grid B, block 128.
//   Per tail: 3 dot products (p63, o~, t~) + algebraic epilogue. syy via
//   orthogonality: syy = 2*x0^2 - 1 + (fs^2-1)*(x.p63)^2.
// ============================================================================
__global__ void __launch_bounds__(TMAIN) k_main(
    const float* __restrict__ ent, const float* __restrict__ bias_tail,
    const int* __restrict__ r_idx, const int* __restrict__ v_idx,
    const float* __restrict__ fst,
    float* __restrict__ out, int N)
{
    __shared__ __align__(16) float pv[DD], ov[DD], tl[DD];
    __shared__ float off_f[DD], th_f[DD];

    int b = blockIdx.x;
    int tid = threadIdx.x;
    int r = r_idx[b];

    if (tid < DD) {
        pv[tid]    = g_p63[r * DD + tid];
        ov[tid]    = g_ofu[r * DD + tid];
        tl[tid]    = g_ttl[b * DD + tid];
        off_f[tid] = g_off[1][r * DD + tid];
        th_f[tid]  = g_th[b * DD + tid];
    }
    float off2 = g_off2[1][r];
    float thb  = g_thb[b];
    float fs   = fst[0];
    float fsm1 = fs * fs - 1.0f;
    __syncthreads();

    // per-block scalar constants over c>=1 (redundant per thread, broadcast LDS)
    float O2m = 0, OTm = 0, T2m = 0;
    #pragma unroll
    for (int c = 1; c < DD; c++) {
        float o = off_f[c], t = th_f[c];
        O2m = fmaf(o, o, O2m);
        OTm = fmaf(o, t, OTm);
        T2m = fmaf(t, t, T2m);
    }
    float off0 = off_f[0], th0 = th_f[0];

    const float4* pv4 = (const float4*)pv;
    const float4* ov4 = (const float4*)ov;
    const float4* tl4 = (const float4*)tl;

    for (int n = tid; n < N; n += TMAIN) {
        int v = v_idx[b * N + n];
        const float4* xr = (const float4*)(ent + (size_t)v * DD);

        float s1a = 0, s1b = 0, s2a = 0, s2b = 0, s3a = 0, s3b = 0;
        float y0 = 0.0f;
        #pragma unroll
        for (int q = 0; q < 16; q++) {
            float4 x4 = xr[q];
            float4 p4 = pv4[q];
            float4 o4 = ov4[q];
            float4 t4 = tl4[q];
            if (q == 0) y0 = x4.x;
            s1a = fmaf(x4.x, p4.x, s1a);  s1b = fmaf(x4.y, p4.y, s1b);
            s1a = fmaf(x4.z, p4.z, s1a);  s1b = fmaf(x4.w, p4.w, s1b);
            s2a = fmaf(x4.x, o4.x, s2a);  s2b = fmaf(x4.y, o4.y, s2b);
            s2a = fmaf(x4.z, o4.z, s2a);  s2b = fmaf(x4.w, o4.w, s2b);
            s3a = fmaf(x4.x, t4.x, s3a);  s3b = fmaf(x4.y, t4.y, s3b);
            s3a = fmaf(x4.z, t4.z, s3a);  s3b = fmaf(x4.w, t4.w, s3b);
        }
        float s1  = s1a + s1b;          // x . p63 (unscaled last col)
        float syo = s2a + s2b;          // includes x0*off0 (folded into ov[0])
        float syt = s3a + s3b;          // c>=1 only

        float syy_m = fmaf(fsm1, s1 * s1, fmaf(y0, y0, -1.0f));  // syy - y0^2
        float syy   = syy_m + y0 * y0;

        float A   = 1.0f + 2.0f * syo + off2;
        float Bv  = 1.0f - syy;
        float den = 1.0f + 2.0f * syo + syy * off2 + 1e-15f;
        float rd  = 1.0f / den;
        float a   = A * rd, bs = Bv * rd;
        float d0  = fmaf(a, y0, fmaf(bs, off0, -th0));
        float cross = fmaf(bs, syo - y0 * off0, -syt);
        float bterm = fmaf(bs, fmaf(bs, O2m, -2.0f * OTm), T2m);
        float sum1  = fmaf(a * a, syy_m, fmaf(2.0f * a, cross, bterm));
        float mkv   = sum1 - d0 * d0;

        float btv = tanhf(bias_tail[v]);
        out[(size_t)b * N + n] = 8.0f - mkv + thb + btv;
    }
}

// ============================================================================
extern "C" void kernel_launch(void* const* d_in, const int* in_sizes, int n_in,
                              void* d_out, int out_size)
{
    (void)n_in; (void)out_size;
    const float* ent  = (const float*)d_in[0];
    const float* Wh   = (const float*)d_in[1];
    const float* Wtt  = (const float*)d_in[2];
    const float* rch  = (const float*)d_in[3];
    const float* dirh = (const float*)d_in[4];
    const float* rct  = (const float*)d_in[5];
    const float* dirt = (const float*)d_in[6];
    const float* bh   = (const float*)d_in[7];
    const float* bt   = (const float*)d_in[8];
    const float* fsh  = (const float*)d_in[9];
    const float* fst  = (const float*)d_in[10];
    const int* u_idx  = (const int*)d_in[11];
    const int* r_idx  = (const int*)d_in[12];
    const int* v_idx  = (const int*)d_in[13];
    float* out = (float*)d_out;

    int NR = in_sizes[3] / DD;       // 237
    int B  = in_sizes[11];           // 1024
    int N  = in_sizes[13] / B;       // 512

    int total_g = 2 * NR * DM * DD;
    k_gelu<<<(total_g + 255) / 256, 256>>>(Wh, Wtt, NR);
    k_rel<<<dim3(NR, 2), 64>>>(rch, dirh, rct, dirt, fsh, fst);
    k_th<<<B, 64>>>(ent, bh, u_idx, r_idx);
    k_main<<<B, TMAIN>>>(ent, bt, r_idx, v_idx, fst, out, N);
}